// round 5
// baseline (speedup 1.0000x reference)
#include <cuda_runtime.h>
#include <cfloat>
#include <math.h>
#include <stdint.h>

// Problem constants (fixed shapes from reference)
#define BB 4
#define NN 4096
#define KK 20
#define PP (BB * NN * KK)     // 327680 positions
#define BN_TOT (BB * NN)      // 16384 (b,n) pairs
#define NB1 (PP / 256)        // layer1 blocks = 1280
#define NBG (PP / 128)        // gemm64 blocks = 2560
#define NB3 (PP / 160)        // gemm3 blocks  = 2048 (8 k-groups per block)

// ---------------------------------------------------------------------------
// Scratch in __device__ globals (no allocation allowed in kernel_launch)
// ---------------------------------------------------------------------------
__device__ float g_y1[64  * PP];
__device__ float g_y2[128 * PP];
__device__ int   g_idx[BB * NN * KK];
__device__ float g_mx[128 * BN_TOT];   // per-(o,bn) max over k (pre-affine)
__device__ float g_mn[128 * BN_TOT];   // per-(o,bn) min over k (pre-affine)
__device__ float g_ps[128 * NBG];
__device__ float g_pq[128 * NBG];
__device__ float g_sc1[64],  g_sh1[64];
__device__ float g_sc2[128], g_sh2[128];
__device__ float g_sc3[128], g_sh3[128];

// ---------------------------------------------------------------------------
// K0: brute-force exact kNN (k=20) per batch (proven version).
// ---------------------------------------------------------------------------
__global__ void knn_kernel(const float* __restrict__ x, int* __restrict__ idxo)
{
    extern __shared__ float4 pts[];   // 4096 * 16B = 64KB
    const int b = blockIdx.y;
    const float* xb = x + (size_t)b * NN * 3;
    for (int t = threadIdx.x; t < NN; t += blockDim.x) {
        float px = xb[t * 3 + 0], py = xb[t * 3 + 1], pz = xb[t * 3 + 2];
        pts[t] = make_float4(px, py, pz, px * px + py * py + pz * pz);
    }
    __syncthreads();

    const int i = blockIdx.x * blockDim.x + threadIdx.x;
    float4 q = pts[i];
    const float qx = 2.f * q.x, qy = 2.f * q.y, qz = 2.f * q.z;

    float bs[KK]; int bi[KK];
#pragma unroll
    for (int t = 0; t < KK; t++) { bs[t] = -FLT_MAX; bi[t] = 0x7fffffff; }
    float wmin = -FLT_MAX;

#pragma unroll 4
    for (int j = 0; j < NN; ++j) {
        float4 p = pts[j];
        float s = fmaf(qx, p.x, fmaf(qy, p.y, fmaf(qz, p.z, -p.w)));
        if (s > wmin) {
            int   ws = 0;
            float wv = bs[0];
            int   wi = bi[0];
#pragma unroll
            for (int t = 1; t < KK; t++) {
                bool worse = (bs[t] < wv) || (bs[t] == wv && bi[t] > wi);
                if (worse) { ws = t; wv = bs[t]; wi = bi[t]; }
            }
            float nm = FLT_MAX;
#pragma unroll
            for (int t = 0; t < KK; t++) {
                if (t == ws) { bs[t] = s; bi[t] = j; }
                nm = fminf(nm, bs[t]);
            }
            wmin = nm;
        }
    }

    int* o = idxo + ((size_t)b * NN + i) * KK;
#pragma unroll
    for (int t = 0; t < KK; t++) o[t] = bi[t];
}

// ---------------------------------------------------------------------------
// K1: edge features -> conv1 (64x6) + BN1 partials (proven version).
// ---------------------------------------------------------------------------
__global__ void __launch_bounds__(256) layer1_kernel(
    const float* __restrict__ x,
    const int* __restrict__ idx,
    const float* __restrict__ W1,
    const float* __restrict__ b1,
    float* __restrict__ y1,
    float* __restrict__ ps,
    float* __restrict__ pq)
{
    __shared__ float Wsh[64 * 6];
    __shared__ float bsh[64];
    __shared__ float s_s[64 * 8];
    __shared__ float s_q[64 * 8];
    for (int t = threadIdx.x; t < 64 * 6; t += blockDim.x) Wsh[t] = W1[t];
    if (threadIdx.x < 64) bsh[threadIdx.x] = b1[threadIdx.x];
    __syncthreads();

    const int tid  = threadIdx.x;
    const int lane = tid & 31;
    const int warp = tid >> 5;
    const int p  = blockIdx.x * 256 + tid;
    const int bn = p / KK;
    const int b  = bn / NN;
    const int j  = idx[p];

    const float* xi = x + (size_t)bn * 3;
    const float* xj = x + ((size_t)b * NN + j) * 3;
    float xi0 = xi[0], xi1 = xi[1], xi2 = xi[2];
    float f0 = xj[0] - xi0, f1 = xj[1] - xi1, f2 = xj[2] - xi2;

#pragma unroll 4
    for (int o = 0; o < 64; ++o) {
        const float* w = Wsh + o * 6;
        float a = bsh[o];
        a = fmaf(w[0], f0, a);
        a = fmaf(w[1], f1, a);
        a = fmaf(w[2], f2, a);
        a = fmaf(w[3], xi0, a);
        a = fmaf(w[4], xi1, a);
        a = fmaf(w[5], xi2, a);
        y1[(size_t)o * PP + p] = a;

        float s = a, q = a * a;
#pragma unroll
        for (int m = 16; m > 0; m >>= 1) {
            s += __shfl_xor_sync(0xffffffffu, s, m);
            q += __shfl_xor_sync(0xffffffffu, q, m);
        }
        if (lane == 0) { s_s[o * 8 + warp] = s; s_q[o * 8 + warp] = q; }
    }
    __syncthreads();

    if (tid < 64) {
        float acc = 0.f;
#pragma unroll
        for (int w = 0; w < 8; w++) acc += s_s[tid * 8 + w];
        ps[tid * NB1 + blockIdx.x] = acc;
    } else if (tid < 128) {
        const int o = tid - 64;
        float acc = 0.f;
#pragma unroll
        for (int w = 0; w < 8; w++) acc += s_q[o * 8 + w];
        pq[o * NB1 + blockIdx.x] = acc;
    }
}

// ---------------------------------------------------------------------------
// Reduce per-block partials -> fused BN affine (scale, shift).
// ---------------------------------------------------------------------------
__global__ void reduce_kernel(const float* __restrict__ ps,
                              const float* __restrict__ pq,
                              int nb,
                              const float* __restrict__ gamma,
                              const float* __restrict__ beta,
                              float* __restrict__ scale,
                              float* __restrict__ shift)
{
    const int c = blockIdx.x;
    double s = 0.0, q = 0.0;
    for (int i = threadIdx.x; i < nb; i += 256) {
        s += (double)ps[c * nb + i];
        q += (double)pq[c * nb + i];
    }
    __shared__ double r1[256], r2[256];
    r1[threadIdx.x] = s; r2[threadIdx.x] = q;
    __syncthreads();
    for (int off = 128; off > 0; off >>= 1) {
        if (threadIdx.x < off) {
            r1[threadIdx.x] += r1[threadIdx.x + off];
            r2[threadIdx.x] += r2[threadIdx.x + off];
        }
        __syncthreads();
    }
    if (threadIdx.x == 0) {
        double mean = r1[0] / (double)PP;
        double var  = r2[0] / (double)PP - mean * mean;
        double inv  = (double)gamma[c] / sqrt(var + 1e-5);
        scale[c] = (float)inv;
        shift[c] = (float)((double)beta[c] - mean * inv);
    }
}

// ---------------------------------------------------------------------------
// GEMM layer2 (CIN=64 -> 128 out), 128-wide tiles, scalar FFMA (proven).
// ---------------------------------------------------------------------------
__global__ void __launch_bounds__(256, 2) gemm2_kernel(
    const float* __restrict__ yin,
    const float* __restrict__ W,
    const float* __restrict__ bias,
    const float* __restrict__ scale,
    const float* __restrict__ shift,
    float* __restrict__ yout,
    float* __restrict__ ps,
    float* __restrict__ pq)
{
    extern __shared__ float sh[];
    float* Wsh = sh;                  // transposed [64][132]
    float* Ash = sh + 132 * 64;       // [64][128]
    const int tid = threadIdx.x;

    for (int t = tid; t < 128 * 64; t += 256) {
        int o = t >> 6, c = t & 63;
        Wsh[c * 132 + o] = W[t];
    }

    const int pbase = blockIdx.x * 128;
    const int tx = tid & 15;
    const int ty = tid >> 4;

    float acc[8][8];
#pragma unroll
    for (int i = 0; i < 8; i++)
#pragma unroll
        for (int j = 0; j < 8; j++) acc[i][j] = 0.f;

    __syncthreads();
    for (int t = tid; t < 64 * 128; t += 256) {
        int c = t >> 7, p = t & 127;
        float v = yin[(size_t)c * PP + pbase + p];
        v = fmaf(v, scale[c], shift[c]);
        Ash[t] = fmaxf(v, 0.f);
    }
    __syncthreads();

#pragma unroll 4
    for (int c = 0; c < 64; ++c) {
        float4 a0 = *(const float4*)(Ash + c * 128 + tx * 4);
        float4 a1 = *(const float4*)(Ash + c * 128 + 64 + tx * 4);
        float4 w0 = *(const float4*)(Wsh + c * 132 + ty * 4);
        float4 w1 = *(const float4*)(Wsh + c * 132 + 64 + ty * 4);
        float a[8] = {a0.x, a0.y, a0.z, a0.w, a1.x, a1.y, a1.z, a1.w};
        float w[8] = {w0.x, w0.y, w0.z, w0.w, w1.x, w1.y, w1.z, w1.w};
#pragma unroll
        for (int i = 0; i < 8; i++)
#pragma unroll
            for (int j = 0; j < 8; j++)
                acc[i][j] = fmaf(w[i], a[j], acc[i][j]);
    }

#pragma unroll
    for (int i = 0; i < 8; i++) {
        const int o = (i < 4) ? (ty * 4 + i) : (64 + ty * 4 + (i - 4));
        const float bo = bias[o];
        float v0 = acc[i][0] + bo, v1 = acc[i][1] + bo;
        float v2 = acc[i][2] + bo, v3 = acc[i][3] + bo;
        float v4 = acc[i][4] + bo, v5 = acc[i][5] + bo;
        float v6 = acc[i][6] + bo, v7 = acc[i][7] + bo;
        float* dst = yout + (size_t)o * PP + pbase;
        *(float4*)(dst + tx * 4)      = make_float4(v0, v1, v2, v3);
        *(float4*)(dst + 64 + tx * 4) = make_float4(v4, v5, v6, v7);

        float s = v0 + v1 + v2 + v3 + v4 + v5 + v6 + v7;
        float q = v0 * v0 + v1 * v1 + v2 * v2 + v3 * v3
                + v4 * v4 + v5 * v5 + v6 * v6 + v7 * v7;
#pragma unroll
        for (int m = 8; m > 0; m >>= 1) {
            s += __shfl_xor_sync(0xffffffffu, s, m, 16);
            q += __shfl_xor_sync(0xffffffffu, q, m, 16);
        }
        if (tx == 0) {
            ps[(size_t)o * NBG + blockIdx.x] = s;
            pq[(size_t)o * NBG + blockIdx.x] = q;
        }
    }
}

// ---------------------------------------------------------------------------
// GEMM layer3 (CIN=128 -> 128 out) with fused max/min-over-k epilogue.
// 160-wide position tiles (= 8 whole k-groups). 512 threads; each thread
// computes 8 outputs x 5 consecutive positions. k-group = 4-lane quad.
// Emits: per-(o,bn) max & min (pre-affine), per-block BN3 partial sums.
// y3 is NEVER materialized (saves 336MB of DRAM traffic vs y3+maxk).
// ---------------------------------------------------------------------------
__global__ void __launch_bounds__(512) gemm3_kernel(
    const float* __restrict__ yin,
    const float* __restrict__ W,
    const float* __restrict__ bias,
    const float* __restrict__ scale,
    const float* __restrict__ shift,
    float* __restrict__ mx,
    float* __restrict__ mn,
    float* __restrict__ ps,
    float* __restrict__ pq)
{
    extern __shared__ float sh[];
    float* Wsh = sh;                  // transposed [128][132]
    float* Ash = sh + 132 * 128;      // [64][160] k-chunk
    const int tid = threadIdx.x;

    for (int t = tid; t < 128 * 128; t += 512) {
        int o = t >> 7, c = t & 127;
        Wsh[c * 132 + o] = W[t];
    }

    const int pbase = blockIdx.x * 160;
    const int tx = tid & 31;   // 32 lane-cols x 5 positions = 160
    const int ty = tid >> 5;   // 16 rows x 8 outputs (4 + 4 split) = 128

    float acc[8][5];
#pragma unroll
    for (int i = 0; i < 8; i++)
#pragma unroll
        for (int j = 0; j < 5; j++) acc[i][j] = 0.f;

#pragma unroll
    for (int kc = 0; kc < 2; ++kc) {
        __syncthreads();   // Wsh ready (kc=0) / protect Ash before restage
        for (int t = tid; t < 64 * 160; t += 512) {
            int c = t / 160, p = t - c * 160;
            int cg = kc * 64 + c;
            float v = yin[(size_t)cg * PP + pbase + p];
            v = fmaf(v, scale[cg], shift[cg]);
            Ash[t] = fmaxf(v, 0.f);
        }
        __syncthreads();

#pragma unroll 4
        for (int c = 0; c < 64; ++c) {
            const int cg = kc * 64 + c;
            float a[5];
#pragma unroll
            for (int j = 0; j < 5; j++) a[j] = Ash[c * 160 + tx * 5 + j];
            float4 w0 = *(const float4*)(Wsh + cg * 132 + ty * 4);
            float4 w1 = *(const float4*)(Wsh + cg * 132 + 64 + ty * 4);
            float w[8] = {w0.x, w0.y, w0.z, w0.w, w1.x, w1.y, w1.z, w1.w};
#pragma unroll
            for (int i = 0; i < 8; i++)
#pragma unroll
                for (int j = 0; j < 5; j++)
                    acc[i][j] = fmaf(w[i], a[j], acc[i][j]);
        }
    }

    const int g  = tx >> 2;                 // k-group within tile (0..7)
    const int bn = blockIdx.x * 8 + g;      // global (b*N+n) index

#pragma unroll
    for (int i = 0; i < 8; i++) {
        const int o = (i < 4) ? (ty * 4 + i) : (64 + ty * 4 + (i - 4));
        const float bo = bias[o];
        float v0 = acc[i][0] + bo, v1 = acc[i][1] + bo, v2 = acc[i][2] + bo;
        float v3 = acc[i][3] + bo, v4 = acc[i][4] + bo;

        // BN3 partials over the whole 160-tile (full-warp reduce; ty fixed/warp)
        float s = v0 + v1 + v2 + v3 + v4;
        float q = v0 * v0 + v1 * v1 + v2 * v2 + v3 * v3 + v4 * v4;
#pragma unroll
        for (int m = 16; m > 0; m >>= 1) {
            s += __shfl_xor_sync(0xffffffffu, s, m);
            q += __shfl_xor_sync(0xffffffffu, q, m);
        }
        if (tx == 0) {
            ps[(size_t)o * NB3 + blockIdx.x] = s;
            pq[(size_t)o * NB3 + blockIdx.x] = q;
        }

        // max/min over the k=20 group (this lane's 5 + quad of 4 lanes)
        float hi = fmaxf(fmaxf(fmaxf(v0, v1), fmaxf(v2, v3)), v4);
        float lo = fminf(fminf(fminf(v0, v1), fminf(v2, v3)), v4);
        hi = fmaxf(hi, __shfl_xor_sync(0xffffffffu, hi, 1, 4));
        hi = fmaxf(hi, __shfl_xor_sync(0xffffffffu, hi, 2, 4));
        lo = fminf(lo, __shfl_xor_sync(0xffffffffu, lo, 1, 4));
        lo = fminf(lo, __shfl_xor_sync(0xffffffffu, lo, 2, 4));
        if ((tx & 3) == 0) {
            mx[(size_t)o * BN_TOT + bn] = hi;
            mn[(size_t)o * BN_TOT + bn] = lo;
        }
    }
}

// ---------------------------------------------------------------------------
// Finalize: out[b][o][n] = sc>=0 ? sc*max+sf : sc*min+sf  (monotone affine).
// ---------------------------------------------------------------------------
__global__ void finalize_kernel(const float* __restrict__ mx,
                                const float* __restrict__ mn,
                                const float* __restrict__ scale,
                                const float* __restrict__ shift,
                                float* __restrict__ out)
{
    const int t  = blockIdx.x * 256 + threadIdx.x;   // 0 .. 128*BN_TOT-1
    const int o  = t >> 14;          // /16384
    const int bn = t & (BN_TOT - 1);
    const int b  = bn >> 12;         // /4096
    const int n  = bn & (NN - 1);
    const float sc = scale[o], sf = shift[o];
    const float v = (sc >= 0.f) ? mx[t] : mn[t];
    out[((size_t)b * 128 + o) * NN + n] = fmaf(sc, v, sf);
}

// ---------------------------------------------------------------------------
// Launcher: graph-capturable, allocation-free.
// ---------------------------------------------------------------------------
extern "C" void kernel_launch(void* const* d_in, const int* in_sizes, int n_in,
                              void* d_out, int out_size)
{
    const float* x   = (const float*)d_in[0];
    const float* W1  = (const float*)d_in[1];
    const float* b1  = (const float*)d_in[2];
    const float* g1  = (const float*)d_in[3];
    const float* be1 = (const float*)d_in[4];
    const float* W2  = (const float*)d_in[5];
    const float* b2  = (const float*)d_in[6];
    const float* g2  = (const float*)d_in[7];
    const float* be2 = (const float*)d_in[8];
    const float* W3  = (const float*)d_in[9];
    const float* b3  = (const float*)d_in[10];
    const float* g3  = (const float*)d_in[11];
    const float* be3 = (const float*)d_in[12];
    float* out = (float*)d_out;

    void *y1p, *y2p, *idxp, *mxp, *mnp, *psp, *pqp;
    void *sc1p, *sh1p, *sc2p, *sh2p, *sc3p, *sh3p;
    cudaGetSymbolAddress(&y1p,  g_y1);
    cudaGetSymbolAddress(&y2p,  g_y2);
    cudaGetSymbolAddress(&idxp, g_idx);
    cudaGetSymbolAddress(&mxp,  g_mx);
    cudaGetSymbolAddress(&mnp,  g_mn);
    cudaGetSymbolAddress(&psp,  g_ps);
    cudaGetSymbolAddress(&pqp,  g_pq);
    cudaGetSymbolAddress(&sc1p, g_sc1);  cudaGetSymbolAddress(&sh1p, g_sh1);
    cudaGetSymbolAddress(&sc2p, g_sc2);  cudaGetSymbolAddress(&sh2p, g_sh2);
    cudaGetSymbolAddress(&sc3p, g_sc3);  cudaGetSymbolAddress(&sh3p, g_sh3);

    const int smem2 = (132 * 64  + 64 * 128) * 4;   // 66560 B
    const int smem3 = (132 * 128 + 64 * 160) * 4;   // 108544 B
    cudaFuncSetAttribute(knn_kernel,   cudaFuncAttributeMaxDynamicSharedMemorySize, 65536);
    cudaFuncSetAttribute(gemm2_kernel, cudaFuncAttributeMaxDynamicSharedMemorySize, smem2);
    cudaFuncSetAttribute(gemm3_kernel, cudaFuncAttributeMaxDynamicSharedMemorySize, smem3);

    // K0: kNN
    knn_kernel<<<dim3(NN / 128, BB), 128, 65536>>>(x, (int*)idxp);

    // K1: edge features + conv1 (raw) + BN1 partials
    layer1_kernel<<<NB1, 256>>>(x, (const int*)idxp, W1, b1, (float*)y1p,
                                (float*)psp, (float*)pqp);
    reduce_kernel<<<64, 256>>>((const float*)psp, (const float*)pqp, NB1,
                               g1, be1, (float*)sc1p, (float*)sh1p);

    // conv2 on relu(BN1(y1)) + BN2 partials
    gemm2_kernel<<<NBG, 256, smem2>>>((const float*)y1p, W2, b2,
                                      (const float*)sc1p, (const float*)sh1p,
                                      (float*)y2p, (float*)psp, (float*)pqp);
    reduce_kernel<<<128, 256>>>((const float*)psp, (const float*)pqp, NBG,
                                g2, be2, (float*)sc2p, (float*)sh2p);

    // conv3 on relu(BN2(y2)) + fused max/min over k + BN3 partials
    gemm3_kernel<<<NB3, 512, smem3>>>((const float*)y2p, W3, b3,
                                      (const float*)sc2p, (const float*)sh2p,
                                      (float*)mxp, (float*)mnp,
                                      (float*)psp, (float*)pqp);
    reduce_kernel<<<128, 256>>>((const float*)psp, (const float*)pqp, NB3,
                                g3, be3, (float*)sc3p, (float*)sh3p);

    // BN3 affine + select max/min
    finalize_kernel<<<(128 * BN_TOT) / 256, 256>>>((const float*)mxp,
                                                   (const float*)mnp,
                                                   (const float*)sc3p,
                                                   (const float*)sh3p,
                                                   out);
}